// round 8
// baseline (speedup 1.0000x reference)
#include <cuda_runtime.h>
#include <math.h>

// BPR loss:
//   per_sample[b] = -( sum_{i<L, j<L, k<S} log_sigmoid( out[b,i,lab[b,j]] - out[b,i,neg[b,j,k]] ) ) / (L^2 * S)
//   result = sum_b per_sample[b]     (shape [1], float32)
//
// Inputs (harness delivers int64 as int32):
//   d_in[0] output  : float32 [B, T, V]
//   d_in[1] labels  : int32   [B, T]
//   d_in[2] x_lens  : int32   [B]
//   d_in[3] uids    : int32   [B, 1]  (unused)
//   d_in[4] neg_ids : int32   [B, T, S]
//
// R8 = R6 main kernel (256 threads, __ldcg gathers; 32.5us, DRAM 69%) + the
// R7 done-counter fusion (last block publishes d_out and resets state, so no
// separate zero kernel; deterministic and graph-replay safe). R7 showed the
// 128-thread block starves the outstanding-gather pool (DRAM 69%->55%), so
// blockDim stays 256.

__device__ float        g_acc  = 0.0f;
__device__ unsigned int g_done = 0u;

__device__ __forceinline__ float warp_reduce_add(float v) {
#pragma unroll
    for (int off = 16; off > 0; off >>= 1)
        v += __shfl_down_sync(0xFFFFFFFFu, v, off);
    return v;
}

__device__ __forceinline__ float log_sigmoid_fast(float d) {
    // min(d,0) - log(1 + exp(-|d|)); exp arg <= 0 so log arg in (1,2]
    return fminf(d, 0.0f) - __logf(1.0f + __expf(-fabsf(d)));
}

__global__ void __launch_bounds__(256)
bpr_loss_kernel(const float* __restrict__ out3d,   // [B,T,V]
                const int* __restrict__ labels,    // [B,T]
                const int* __restrict__ x_lens,    // [B]
                const int* __restrict__ neg_ids,   // [B,T,S]
                float* __restrict__ result,        // [1]
                int T, int V, int S)
{
    const int b = blockIdx.y;
    const int i = blockIdx.x;
    const int L = x_lens[b];

    float acc = 0.0f;
    if (i < L) {
        const float* __restrict__ row = out3d + ((size_t)b * T + i) * (size_t)V;
        const int* __restrict__ lab = labels + (size_t)b * T;
        const int* __restrict__ neg = neg_ids + (size_t)b * T * S;

        if (S == 1) {
            for (int j = threadIdx.x; j < L; j += blockDim.x) {
                const int c_pos = __ldg(lab + j);
                const int c_neg = __ldg(neg + j);
                const float pv = __ldcg(row + c_pos);
                const float nv = __ldcg(row + c_neg);
                acc += log_sigmoid_fast(pv - nv);
            }
        } else {
            for (int j = threadIdx.x; j < L; j += blockDim.x) {
                const float pv = __ldcg(row + __ldg(lab + j));
                for (int k = 0; k < S; ++k)
                    acc += log_sigmoid_fast(pv - __ldcg(row + __ldg(neg + (size_t)j * S + k)));
            }
        }
    }

    // block reduction (every block, including dead rows, reaches the counter)
    __shared__ float warp_sums[8];
    const int lane = threadIdx.x & 31;
    const int wid  = threadIdx.x >> 5;
    acc = warp_reduce_add(acc);
    if (lane == 0) warp_sums[wid] = acc;
    __syncthreads();

    if (wid == 0) {
        float v = (lane < 8) ? warp_sums[lane] : 0.0f;
        v = warp_reduce_add(v);
        if (lane == 0) {
            if (i < L) {
                const float Lf = (float)L;
                atomicAdd(&g_acc, v * (-1.0f / (Lf * Lf * (float)S)));
            }
            __threadfence();
            const unsigned int total = gridDim.x * gridDim.y;
            const unsigned int ticket = atomicAdd(&g_done, 1u);
            if (ticket == total - 1u) {
                // last block: publish and reset state for the next launch
                result[0] = g_acc;
                g_acc  = 0.0f;
                g_done = 0u;
            }
        }
    }
}

extern "C" void kernel_launch(void* const* d_in, const int* in_sizes, int n_in,
                              void* d_out, int out_size)
{
    const float* out3d   = (const float*)d_in[0];
    const int*   labels  = (const int*)d_in[1];
    const int*   x_lens  = (const int*)d_in[2];
    const int*   neg_ids = (const int*)d_in[4];
    float* result = (float*)d_out;

    const int B = in_sizes[2];                 // x_lens: B
    const int T = in_sizes[1] / B;             // labels: B*T
    const int V = in_sizes[0] / (B * T);       // output: B*T*V
    const int S = in_sizes[4] / (B * T);       // neg_ids: B*T*S

    dim3 grid(T, B);
    bpr_loss_kernel<<<grid, 256>>>(out3d, labels, x_lens, neg_ids, result, T, V, S);
}

// round 9
// speedup vs baseline: 1.0347x; 1.0347x over previous
#include <cuda_runtime.h>
#include <math.h>

// BPR loss:
//   per_sample[b] = -( sum_{i<L, j<L, k<S} log_sigmoid( out[b,i,lab[b,j]] - out[b,i,neg[b,j,k]] ) ) / (L^2 * S)
//   result = sum_b per_sample[b]     (shape [1], float32)
//
// Inputs (harness delivers int64 as int32):
//   d_in[0] output  : float32 [B, T, V]
//   d_in[1] labels  : int32   [B, T]
//   d_in[2] x_lens  : int32   [B]
//   d_in[3] uids    : int32   [B, 1]  (unused)
//   d_in[4] neg_ids : int32   [B, T, S]
//
// R9 = R6 main kernel exactly (proven: main 32.5us, DRAM 69% = random-gather
// floor), with the zero-kernel replaced by a cudaMemsetAsync graph node.
// NO device-scope fences anywhere: R7/R8 proved __threadfence's CCTL.IVALL
// (per-block L1D flush) costs ~8us at this grid size.

__device__ __forceinline__ float warp_reduce_add(float v) {
#pragma unroll
    for (int off = 16; off > 0; off >>= 1)
        v += __shfl_down_sync(0xFFFFFFFFu, v, off);
    return v;
}

__device__ __forceinline__ float log_sigmoid_fast(float d) {
    // min(d,0) - log(1 + exp(-|d|)); exp arg <= 0 so log arg in (1,2]
    return fminf(d, 0.0f) - __logf(1.0f + __expf(-fabsf(d)));
}

__global__ void __launch_bounds__(256)
bpr_loss_kernel(const float* __restrict__ out3d,   // [B,T,V]
                const int* __restrict__ labels,    // [B,T]
                const int* __restrict__ x_lens,    // [B]
                const int* __restrict__ neg_ids,   // [B,T,S]
                float* __restrict__ result,        // [1]
                int T, int V, int S)
{
    const int b = blockIdx.y;
    const int i = blockIdx.x;
    const int L = x_lens[b];
    if (i >= L) return;

    const float* __restrict__ row = out3d + ((size_t)b * T + i) * (size_t)V;
    const int* __restrict__ lab = labels + (size_t)b * T;
    const int* __restrict__ neg = neg_ids + (size_t)b * T * S;

    float acc = 0.0f;
    if (S == 1) {
        for (int j = threadIdx.x; j < L; j += blockDim.x) {
            const int c_pos = __ldg(lab + j);
            const int c_neg = __ldg(neg + j);
            const float pv = __ldcg(row + c_pos);
            const float nv = __ldcg(row + c_neg);
            acc += log_sigmoid_fast(pv - nv);
        }
    } else {
        for (int j = threadIdx.x; j < L; j += blockDim.x) {
            const float pv = __ldcg(row + __ldg(lab + j));
            for (int k = 0; k < S; ++k)
                acc += log_sigmoid_fast(pv - __ldcg(row + __ldg(neg + (size_t)j * S + k)));
        }
    }

    // block reduction
    __shared__ float warp_sums[8];
    const int lane = threadIdx.x & 31;
    const int wid  = threadIdx.x >> 5;
    acc = warp_reduce_add(acc);
    if (lane == 0) warp_sums[wid] = acc;
    __syncthreads();
    if (wid == 0) {
        float v = (lane < 8) ? warp_sums[lane] : 0.0f;
        v = warp_reduce_add(v);
        if (lane == 0) {
            const float Lf = (float)L;
            atomicAdd(result, v * (-1.0f / (Lf * Lf * (float)S)));
        }
    }
}

extern "C" void kernel_launch(void* const* d_in, const int* in_sizes, int n_in,
                              void* d_out, int out_size)
{
    const float* out3d   = (const float*)d_in[0];
    const int*   labels  = (const int*)d_in[1];
    const int*   x_lens  = (const int*)d_in[2];
    const int*   neg_ids = (const int*)d_in[4];
    float* result = (float*)d_out;

    const int B = in_sizes[2];                 // x_lens: B
    const int T = in_sizes[1] / B;             // labels: B*T
    const int V = in_sizes[0] / (B * T);       // output: B*T*V
    const int S = in_sizes[4] / (B * T);       // neg_ids: B*T*S

    // zero the accumulator via a graph memset node (cheaper than a kernel launch)
    cudaMemsetAsync(d_out, 0, sizeof(float), 0);

    dim3 grid(T, B);
    bpr_loss_kernel<<<grid, 256>>>(out3d, labels, x_lens, neg_ids, result, T, V, S);
}